// round 13
// baseline (speedup 1.0000x reference)
#include <cuda_runtime.h>
#include <cuda_fp16.h>
#include <cstdint>
#include <math.h>

#define S   2048
#define D   2048
#define DFF 8192
#define H   16
#define DH  128

// ---------------------------------------------------------------------------
// Scratch (device globals; no allocation allowed)
// ---------------------------------------------------------------------------
__device__ float g_normed[(size_t)S * D];
__device__ float g_x1[(size_t)S * D];

__device__ __half g_qh[(size_t)S * D];
__device__ __half g_kh[(size_t)S * D];
__device__ __half g_vh[(size_t)S * D];
__device__ __half g_gate_h[(size_t)S * DFF];
__device__ __half g_up_h[(size_t)S * DFF];

__device__ __half g_wq_h[(size_t)D * D];
__device__ __half g_wk_h[(size_t)D * D];
__device__ __half g_wv_h[(size_t)D * D];
__device__ __half g_wo_h[(size_t)D * D];
__device__ __half g_wg_h[(size_t)DFF * D];
__device__ __half g_wu_h[(size_t)DFF * D];
__device__ __half g_wd_h[(size_t)D * DFF];
__device__ __half g_act[(size_t)S * DFF];      // fp16 activations (max size)

// ---------------------------------------------------------------------------
// helpers
// ---------------------------------------------------------------------------
__device__ __forceinline__ uint32_t smem_u32(const void* p) {
    uint32_t a;
    asm("{ .reg .u64 t; cvta.to.shared.u64 t, %1; cvt.u32.u64 %0, t; }"
        : "=r"(a) : "l"(p));
    return a;
}

__device__ __forceinline__ uint32_t packh(float x, float y) {
    __half2 t = __floats2half2_rn(x, y);
    return *(uint32_t*)&t;
}

__device__ __forceinline__ void mma16816h(float* c, const uint32_t* a,
                                          uint32_t b0, uint32_t b1) {
    asm volatile(
        "mma.sync.aligned.m16n8k16.row.col.f32.f16.f16.f32 "
        "{%0,%1,%2,%3}, {%4,%5,%6,%7}, {%8,%9}, {%0,%1,%2,%3};"
        : "+f"(c[0]), "+f"(c[1]), "+f"(c[2]), "+f"(c[3])
        : "r"(a[0]), "r"(a[1]), "r"(a[2]), "r"(a[3]), "r"(b0), "r"(b1));
}

// ---------------------------------------------------------------------------
// Segmented weight GEMM via mma.sync (fp16 in, fp32 accum).  FROZEN CONFIG.
// CTA 128x128, BK=32, 8 warps (2x4), warp tile 64x32, 3-stage cp.async,
// stage 16KB (48KB total, 2 CTA/SM). Up to 3 segments per launch.
// ---------------------------------------------------------------------------
#define TILE_B   8192
#define STAGE_B  (2 * TILE_B)
#define MMA_SMEM (3 * STAGE_B)

struct GemmSegs {
    const __half* B[3];
    __half*       Ch[3];
    const float*  scale[3];
    float         sconst[3];
    float*        Cf;
    const float*  R;
};

__device__ __forceinline__ uint32_t sw_addr(uint32_t s_tile, int row, int ck) {
    return s_tile + row * 64 + ((ck ^ ((row >> 1) & 3)) << 4);
}

__device__ __forceinline__ void cp_tile(
    uint32_t s_tile, const __half* __restrict__ g,
    int row0, int ld, int k0, int tid)
{
#pragma unroll
    for (int i = 0; i < 2; i++) {
        const int idx = tid + i * 256;
        const int r   = idx >> 2;
        const int ck  = idx & 3;
        const void* src = g + (size_t)(row0 + r) * ld + k0 + ck * 8;
        const uint32_t dst = s_tile + r * 64 + (((ck ^ ((r >> 1) & 3))) << 4);
        asm volatile("cp.async.cg.shared.global [%0], [%1], 16;"
                     :: "r"(dst), "l"(src));
    }
}

__device__ __forceinline__ void load_stage(
    uint32_t stg, const __half* A, const __half* Bw,
    int rowA0, int rowB0, int Ktot, int k0, int tid)
{
    cp_tile(stg,          A,  rowA0, Ktot, k0, tid);
    cp_tile(stg + TILE_B, Bw, rowB0, Ktot, k0, tid);
    asm volatile("cp.async.commit_group;");
}

__global__ __launch_bounds__(256)
void mma_gemm(const __half* __restrict__ A,
              GemmSegs p, int nbn_seg, int Ktot, int ldc)
{
    extern __shared__ char smem[];
    const uint32_t sbase = smem_u32(smem);
    const int tid = threadIdx.x;
    const int l   = tid & 31;
    const int w   = tid >> 5;
    const int wm  = w >> 2;
    const int wn  = w & 3;
    const int bm  = blockIdx.y;
    const int seg = blockIdx.x / nbn_seg;
    const int bnl = blockIdx.x % nbn_seg;
    const int rowA0 = bm * 128;
    const int rowB0 = bnl * 128;
    const __half* Bw = p.B[seg];

    float acc[4][4][4];
#pragma unroll
    for (int i = 0; i < 4; i++)
#pragma unroll
        for (int j = 0; j < 4; j++)
#pragma unroll
            for (int c = 0; c < 4; c++) acc[i][j][c] = 0.0f;

    const int nc = Ktot >> 5;

    load_stage(sbase,           A, Bw, rowA0, rowB0, Ktot, 0,  tid);
    load_stage(sbase + STAGE_B, A, Bw, rowA0, rowB0, Ktot, 32, tid);

    for (int c = 0; c < nc; c++) {
        if (c + 2 < nc) {
            load_stage(sbase + ((c + 2) % 3) * STAGE_B, A, Bw,
                       rowA0, rowB0, Ktot, (c + 2) * 32, tid);
            asm volatile("cp.async.wait_group 2;");
        } else if (c + 1 < nc) {
            asm volatile("cp.async.wait_group 1;");
        } else {
            asm volatile("cp.async.wait_group 0;");
        }
        __syncthreads();

        const uint32_t st = sbase + (c % 3) * STAGE_B;
        const uint32_t sA = st;
        const uint32_t sB = st + TILE_B;

#pragma unroll
        for (int ks = 0; ks < 2; ks++) {
            uint32_t bf[4][2];
#pragma unroll
            for (int nf = 0; nf < 4; nf++) {
                const int nrow = wn * 32 + nf * 8 + (l & 7);
                const int ck   = ks * 2 + ((l >> 3) & 1);
                asm volatile(
                    "ldmatrix.sync.aligned.m8n8.x2.shared.b16 {%0,%1}, [%2];"
                    : "=r"(bf[nf][0]), "=r"(bf[nf][1])
                    : "r"(sw_addr(sB, nrow, ck)));
            }
            uint32_t af[4][4];
#pragma unroll
            for (int mf = 0; mf < 4; mf++) {
                const int arow = wm * 64 + mf * 16 + (l & 15);
                const int ck   = ks * 2 + (l >> 4);
                asm volatile(
                    "ldmatrix.sync.aligned.m8n8.x4.shared.b16 {%0,%1,%2,%3}, [%4];"
                    : "=r"(af[mf][0]), "=r"(af[mf][1]),
                      "=r"(af[mf][2]), "=r"(af[mf][3])
                    : "r"(sw_addr(sA, arow, ck)));
            }
#pragma unroll
            for (int mf = 0; mf < 4; mf++)
#pragma unroll
                for (int nf = 0; nf < 4; nf++)
                    mma16816h(acc[mf][nf], af[mf], bf[nf][0], bf[nf][1]);
        }
        __syncthreads();
    }

    float sc = p.sconst[seg];
    if (p.scale[seg]) sc *= __ldg(p.scale[seg]);
    __half* Ch = p.Ch[seg];
    const int qrow = l >> 2;
    const int qcol = (l & 3) * 2;

#pragma unroll
    for (int mf = 0; mf < 4; mf++) {
        const size_t r0 = (size_t)(bm * 128 + wm * 64 + mf * 16 + qrow);
#pragma unroll
        for (int nf = 0; nf < 4; nf++) {
            const size_t c0 = (size_t)(bnl * 128 + wn * 32 + nf * 8 + qcol);
#pragma unroll
            for (int half = 0; half < 2; half++) {
                const size_t row = r0 + half * 8;
                const size_t off = row * ldc + c0;
                float ox = acc[mf][nf][half * 2 + 0] * sc;
                float oy = acc[mf][nf][half * 2 + 1] * sc;
                if (Ch) {
                    *(uint32_t*)(Ch + off) = packh(ox, oy);
                } else {
                    if (p.R) {
                        const float2 rv = *(const float2*)(p.R + off);
                        ox += rv.x; oy += rv.y;
                    }
                    float2 o; o.x = ox; o.y = oy;
                    *(float2*)(p.Cf + off) = o;
                }
            }
        }
    }
}

// ---------------------------------------------------------------------------
// Flash attention (fp16 tensor cores, fp32 online softmax).
// Round-13 changes: (1) longest-job-first: bq = gridDim.x-1-blockIdx.x so
// heavy causal tiles launch first; (2) Q tile kept in smem (not registers),
// fragments re-loaded per KV block -> frees 32 persistent regs.
// smem: [0, 2*FL_STAGE) KV double buffer; [2*FL_STAGE, +32KB) Q tile.
// ---------------------------------------------------------------------------
#define FL_STAGE 65536
#define FL_QOFF  (2 * FL_STAGE)
#define FL_SMEM  (2 * FL_STAGE + 32768)

__device__ __forceinline__ uint32_t sw256(uint32_t base, int row, int ck) {
    return base + row * 256 + (((((ck & 7) ^ (row & 7))) | (ck & 8)) << 4);
}

__device__ __forceinline__ void cp_tile256(
    uint32_t s_tile, const __half* __restrict__ g,
    int row0, int col0, int tid)
{
#pragma unroll
    for (int i = 0; i < 8; i++) {
        const int idx = tid + i * 256;
        const int r  = idx >> 4;
        const int ck = idx & 15;
        const void* src = g + (size_t)(row0 + r) * D + col0 + ck * 8;
        asm volatile("cp.async.cg.shared.global [%0], [%1], 16;"
                     :: "r"(sw256(s_tile, r, ck)), "l"(src));
    }
}

__global__ __launch_bounds__(256)
void flash_attn(const __half* __restrict__ Qh,
                const __half* __restrict__ Kh,
                const __half* __restrict__ Vh,
                const float* __restrict__ normed,
                const float* __restrict__ alpha,
                __half* __restrict__ outh)
{
    extern __shared__ char smem[];
    const uint32_t sbase = smem_u32(smem);
    const int tid = threadIdx.x;
    const int l   = tid & 31;
    const int w   = tid >> 5;
    // longest-job-first: largest bq (most KV blocks) scheduled first
    const int bq  = (int)gridDim.x - 1 - (int)blockIdx.x;
    const int h   = blockIdx.y;
    const int col0 = h * DH;

    // Q tile -> resident smem region (loaded once, stays all kernel)
    cp_tile256(sbase + FL_QOFF, Qh, bq * 128, col0, tid);
    // KV block 0 -> stage 0
    cp_tile256(sbase,         Kh, 0, col0, tid);
    cp_tile256(sbase + 32768, Vh, 0, col0, tid);
    asm volatile("cp.async.commit_group;");

    float oacc[16][4];
#pragma unroll
    for (int i = 0; i < 16; i++)
#pragma unroll
        for (int j = 0; j < 4; j++) oacc[i][j] = 0.0f;
    float m0 = -1e30f, m1 = -1e30f, l0 = 0.0f, l1 = 0.0f;

    for (int kb = 0; kb <= bq; kb++) {
        if (kb + 1 <= bq) {
            const uint32_t nb = sbase + ((kb + 1) & 1) * FL_STAGE;
            asm volatile("cp.async.wait_group 0;");   // prior stage complete
            __syncthreads();
            cp_tile256(nb,         Kh, (kb + 1) * 128, col0, tid);
            cp_tile256(nb + 32768, Vh, (kb + 1) * 128, col0, tid);
            asm volatile("cp.async.commit_group;");
            asm volatile("cp.async.wait_group 1;");
        } else {
            asm volatile("cp.async.wait_group 0;");
        }
        __syncthreads();

        const uint32_t sK = sbase + (kb & 1) * FL_STAGE;
        const uint32_t sV = sK + 32768;
        const uint32_t sQ = sbase + FL_QOFF;

        // ---- S = Q @ K^T  (Q fragments re-loaded from smem per k-chunk)
        float sacc[16][4];
#pragma unroll
        for (int i = 0; i < 16; i++)
#pragma unroll
            for (int j = 0; j < 4; j++) sacc[i][j] = 0.0f;

#pragma unroll
        for (int kk = 0; kk < 8; kk++) {
            uint32_t qf[4];
            {
                const int r  = w * 16 + (l & 15);
                const int ck = kk * 2 + (l >> 4);
                asm volatile(
                    "ldmatrix.sync.aligned.m8n8.x4.shared.b16 {%0,%1,%2,%3}, [%4];"
                    : "=r"(qf[0]), "=r"(qf[1]), "=r"(qf[2]), "=r"(qf[3])
                    : "r"(sw256(sQ, r, ck)));
            }
#pragma unroll
            for (int p = 0; p < 8; p++) {
                uint32_t b[4];
                const int r  = p * 16 + ((l >> 4) << 3) + (l & 7);
                const int ck = kk * 2 + ((l >> 3) & 1);
                asm volatile(
                    "ldmatrix.sync.aligned.m8n8.x4.shared.b16 {%0,%1,%2,%3}, [%4];"
                    : "=r"(b[0]), "=r"(b[1]), "=r"(b[2]), "=r"(b[3])
                    : "r"(sw256(sK, r, ck)));
                mma16816h(sacc[2 * p],     qf, b[0], b[1]);
                mma16816h(sacc[2 * p + 1], qf, b[2], b[3]);
            }
        }

        // ---- causal mask on diagonal block
        if (kb == bq) {
            const int r0 = w * 16 + (l >> 2);
#pragma unroll
            for (int nf = 0; nf < 16; nf++) {
                const int c0 = nf * 8 + (l & 3) * 2;
                if (c0     > r0)     sacc[nf][0] = -1e30f;
                if (c0 + 1 > r0)     sacc[nf][1] = -1e30f;
                if (c0     > r0 + 8) sacc[nf][2] = -1e30f;
                if (c0 + 1 > r0 + 8) sacc[nf][3] = -1e30f;
            }
        }

        // ---- online softmax
        float bm0 = -1e30f, bm1 = -1e30f;
#pragma unroll
        for (int nf = 0; nf < 16; nf++) {
            bm0 = fmaxf(bm0, fmaxf(sacc[nf][0], sacc[nf][1]));
            bm1 = fmaxf(bm1, fmaxf(sacc[nf][2], sacc[nf][3]));
        }
        bm0 = fmaxf(bm0, __shfl_xor_sync(0xFFFFFFFFu, bm0, 1));
        bm0 = fmaxf(bm0, __shfl_xor_sync(0xFFFFFFFFu, bm0, 2));
        bm1 = fmaxf(bm1, __shfl_xor_sync(0xFFFFFFFFu, bm1, 1));
        bm1 = fmaxf(bm1, __shfl_xor_sync(0xFFFFFFFFu, bm1, 2));

        const float nm0 = fmaxf(m0, bm0);
        const float nm1 = fmaxf(m1, bm1);
        const float sf0 = __expf(m0 - nm0);
        const float sf1 = __expf(m1 - nm1);

        float rs0 = 0.0f, rs1 = 0.0f;
#pragma unroll
        for (int nf = 0; nf < 16; nf++) {
            const float p0 = __expf(sacc[nf][0] - nm0);
            const float p1 = __expf(sacc[nf][1] - nm0);
            const float p2 = __expf(sacc[nf][2] - nm1);
            const float p3 = __expf(sacc[nf][3] - nm1);
            sacc[nf][0] = p0; sacc[nf][1] = p1;
            sacc[nf][2] = p2; sacc[nf][3] = p3;
            rs0 += p0 + p1; rs1 += p2 + p3;
        }
        rs0 += __shfl_xor_sync(0xFFFFFFFFu, rs0, 1);
        rs0 += __shfl_xor_sync(0xFFFFFFFFu, rs0, 2);
        rs1 += __shfl_xor_sync(0xFFFFFFFFu, rs1, 1);
        rs1 += __shfl_xor_sync(0xFFFFFFFFu, rs1, 2);

        l0 = l0 * sf0 + rs0;
        l1 = l1 * sf1 + rs1;
        m0 = nm0; m1 = nm1;
#pragma unroll
        for (int nf = 0; nf < 16; nf++) {
            oacc[nf][0] *= sf0; oacc[nf][1] *= sf0;
            oacc[nf][2] *= sf1; oacc[nf][3] *= sf1;
        }

        // ---- O += P @ V
#pragma unroll
        for (int kk = 0; kk < 8; kk++) {
            uint32_t a[4];
            a[0] = packh(sacc[2 * kk][0],     sacc[2 * kk][1]);
            a[1] = packh(sacc[2 * kk][2],     sacc[2 * kk][3]);
            a[2] = packh(sacc[2 * kk + 1][0], sacc[2 * kk + 1][1]);
            a[3] = packh(sacc[2 * kk + 1][2], sacc[2 * kk + 1][3]);
#pragma unroll
            for (int p = 0; p < 8; p++) {
                uint32_t b[4];
                const int r  = kk * 16 + ((l >> 3) & 1) * 8 + (l & 7);
                const int ck = 2 * p + (l >> 4);
                asm volatile(
                    "ldmatrix.sync.aligned.m8n8.x4.trans.shared.b16 {%0,%1,%2,%3}, [%4];"
                    : "=r"(b[0]), "=r"(b[1]), "=r"(b[2]), "=r"(b[3])
                    : "r"(sw256(sV, r, ck)));
                mma16816h(oacc[2 * p],     a, b[0], b[1]);
                mma16816h(oacc[2 * p + 1], a, b[2], b[3]);
            }
        }
        __syncthreads();
    }

    // ---- epilogue: O/l + alpha*normed -> fp16
    const float il0 = 1.0f / l0;
    const float il1 = 1.0f / l1;
    const float al  = __ldg(alpha + h);
    const size_t r0g = (size_t)(bq * 128 + w * 16 + (l >> 2));
    const size_t r1g = r0g + 8;

#pragma unroll
    for (int nf = 0; nf < 16; nf++) {
        const size_t cg = (size_t)(col0 + nf * 8 + (l & 3) * 2);
#pragma unroll
        for (int rr = 0; rr < 2; rr++) {
            const size_t row = rr ? r1g : r0g;
            const float il = rr ? il1 : il0;
            const float v0 = oacc[nf][rr * 2 + 0] * il + al * normed[row * D + cg];
            const float v1 = oacc[nf][rr * 2 + 1] * il + al * normed[row * D + cg + 1];
            *(uint32_t*)(outh + row * D + cg) = packh(v0, v1);
        }
    }
}

// ---------------------------------------------------------------------------
// Fused weight conversion: all 7 weights in one launch.
// ---------------------------------------------------------------------------
struct CvtParams {
    const float* src[7];
    __half*      dst[7];
    int          start[8];
};

__global__ __launch_bounds__(256) void convert_all_kernel(CvtParams p)
{
    const int b = blockIdx.x;
    int seg = 0;
#pragma unroll
    for (int s = 1; s < 7; s++)
        if (b >= p.start[s]) seg = s;
    const int i = (b - p.start[seg]) * 256 + threadIdx.x;
    const float4 v0 = ((const float4*)p.src[seg])[2 * i];
    const float4 v1 = ((const float4*)p.src[seg])[2 * i + 1];
    uint4 o;
    o.x = packh(v0.x, v0.y);
    o.y = packh(v0.z, v0.w);
    o.z = packh(v1.x, v1.y);
    o.w = packh(v1.z, v1.w);
    ((uint4*)p.dst[seg])[i] = o;
}

// rmsnorm -> f32 out + fp16 out, one block per row
__global__ __launch_bounds__(256) void rmsnorm_h_kernel(
    const float* __restrict__ x, const float* __restrict__ w,
    float* __restrict__ outf, __half* __restrict__ outh)
{
    __shared__ float red[256];
    const int r = blockIdx.x;
    const int tid = threadIdx.x;
    const float* xr = x + (size_t)r * D;

    float ss = 0.0f;
#pragma unroll
    for (int j4 = tid; j4 < D / 4; j4 += 256) {
        const float4 v = ((const float4*)xr)[j4];
        ss += v.x * v.x + v.y * v.y + v.z * v.z + v.w * v.w;
    }
    red[tid] = ss;
    __syncthreads();
    for (int s = 128; s > 0; s >>= 1) {
        if (tid < s) red[tid] += red[tid + s];
        __syncthreads();
    }
    const float sc = rsqrtf(red[0] / (float)D + 1e-6f);

#pragma unroll
    for (int j4 = tid; j4 < D / 4; j4 += 256) {
        const float4 v  = ((const float4*)xr)[j4];
        const float4 wv = ((const float4*)w)[j4];
        const float o0 = v.x * sc * wv.x;
        const float o1 = v.y * sc * wv.y;
        const float o2 = v.z * sc * wv.z;
        const float o3 = v.w * sc * wv.w;
        float4 of; of.x = o0; of.y = o1; of.z = o2; of.w = o3;
        ((float4*)(outf + (size_t)r * D))[j4] = of;
        uint2 oh;
        oh.x = packh(o0, o1);
        oh.y = packh(o2, o3);
        ((uint2*)(outh + (size_t)r * D))[j4] = oh;
    }
}

// h = silu(g)*u with fp16 g,u inputs -> fp16 out
__global__ __launch_bounds__(256) void silu_mul_h_kernel(
    const __half* __restrict__ g, const __half* __restrict__ u,
    __half* __restrict__ outh)
{
    const size_t i = (size_t)blockIdx.x * 256 + threadIdx.x;
    const uint2 gv = ((const uint2*)g)[i];
    const uint2 uv = ((const uint2*)u)[i];
    const __half2 g0 = *(const __half2*)&gv.x;
    const __half2 g1 = *(const __half2*)&gv.y;
    const __half2 u0 = *(const __half2*)&uv.x;
    const __half2 u1 = *(const __half2*)&uv.y;
    const float gx = __half2float(g0.x), gy = __half2float(g0.y);
    const float gz = __half2float(g1.x), gw = __half2float(g1.y);
    const float a0 = gx / (1.0f + __expf(-gx)) * __half2float(u0.x);
    const float a1 = gy / (1.0f + __expf(-gy)) * __half2float(u0.y);
    const float a2 = gz / (1.0f + __expf(-gz)) * __half2float(u1.x);
    const float a3 = gw / (1.0f + __expf(-gw)) * __half2float(u1.y);
    uint2 o;
    o.x = packh(a0, a1);
    o.y = packh(a2, a3);
    ((uint2*)outh)[i] = o;
}

// ---------------------------------------------------------------------------
// Launch
// ---------------------------------------------------------------------------
extern "C" void kernel_launch(void* const* d_in, const int* in_sizes, int n_in,
                              void* d_out, int out_size)
{
    (void)in_sizes; (void)n_in; (void)out_size;

    const float* x     = (const float*)d_in[0];
    const float* wn_a  = (const float*)d_in[1];
    const float* wn_m  = (const float*)d_in[2];
    const float* Wq    = (const float*)d_in[3];
    const float* sq    = (const float*)d_in[4];
    const float* Wk    = (const float*)d_in[5];
    const float* sk    = (const float*)d_in[6];
    const float* Wv    = (const float*)d_in[7];
    const float* sv    = (const float*)d_in[8];
    const float* Wo    = (const float*)d_in[9];
    const float* so    = (const float*)d_in[10];
    const float* Wg    = (const float*)d_in[11];
    const float* sg    = (const float*)d_in[12];
    const float* Wu    = (const float*)d_in[13];
    const float* su    = (const float*)d_in[14];
    const float* Wd    = (const float*)d_in[15];
    const float* sd    = (const float*)d_in[16];
    const float* alpha = (const float*)d_in[17];
    float* out = (float*)d_out;

    float *normed, *x1;
    cudaGetSymbolAddress((void**)&normed, g_normed);
    cudaGetSymbolAddress((void**)&x1,     g_x1);

    __half *qh, *kh, *vh, *gateh, *uph, *wq, *wk, *wv, *wo, *wg, *wu, *wd, *act;
    cudaGetSymbolAddress((void**)&qh, g_qh);
    cudaGetSymbolAddress((void**)&kh, g_kh);
    cudaGetSymbolAddress((void**)&vh, g_vh);
    cudaGetSymbolAddress((void**)&gateh, g_gate_h);
    cudaGetSymbolAddress((void**)&uph,   g_up_h);
    cudaGetSymbolAddress((void**)&wq, g_wq_h);
    cudaGetSymbolAddress((void**)&wk, g_wk_h);
    cudaGetSymbolAddress((void**)&wv, g_wv_h);
    cudaGetSymbolAddress((void**)&wo, g_wo_h);
    cudaGetSymbolAddress((void**)&wg, g_wg_h);
    cudaGetSymbolAddress((void**)&wu, g_wu_h);
    cudaGetSymbolAddress((void**)&wd, g_wd_h);
    cudaGetSymbolAddress((void**)&act, g_act);

    cudaFuncSetAttribute(mma_gemm, cudaFuncAttributeMaxDynamicSharedMemorySize,
                         MMA_SMEM);
    cudaFuncSetAttribute(flash_attn, cudaFuncAttributeMaxDynamicSharedMemorySize,
                         FL_SMEM);

    const float inv_sqrt_dh = 0.08838834764831845f;  // 1/sqrt(128)

    // 0. all weights -> fp16 in one launch (exact for ternary)
    const int bDD = D * D / 8 / 256;
    const int bFD = DFF * D / 8 / 256;
    CvtParams cp;
    cp.src[0] = Wq; cp.dst[0] = wq;
    cp.src[1] = Wk; cp.dst[1] = wk;
    cp.src[2] = Wv; cp.dst[2] = wv;
    cp.src[3] = Wo; cp.dst[3] = wo;
    cp.src[4] = Wg; cp.dst[4] = wg;
    cp.src[5] = Wu; cp.dst[5] = wu;
    cp.src[6] = Wd; cp.dst[6] = wd;
    cp.start[0] = 0;
    cp.start[1] = bDD;
    cp.start[2] = 2 * bDD;
    cp.start[3] = 3 * bDD;
    cp.start[4] = 4 * bDD;
    cp.start[5] = 4 * bDD + bFD;
    cp.start[6] = 4 * bDD + 2 * bFD;
    cp.start[7] = 4 * bDD + 3 * bFD;
    convert_all_kernel<<<cp.start[7], 256>>>(cp);

    // 1. rmsnorm (f32 + fp16 fused)
    rmsnorm_h_kernel<<<S, 256>>>(x, wn_a, normed, act);

    // 2. QKV fused: 3 segments, grid (48, 16)
    {
        GemmSegs p = {};
        p.B[0] = wq; p.B[1] = wk; p.B[2] = wv;
        p.Ch[0] = qh; p.Ch[1] = kh; p.Ch[2] = vh;
        p.scale[0] = sq; p.scale[1] = sk; p.scale[2] = sv;
        p.sconst[0] = inv_sqrt_dh; p.sconst[1] = 1.0f; p.sconst[2] = 1.0f;
        mma_gemm<<<dim3(3 * D / 128, S / 128), 256, MMA_SMEM>>>(
            act, p, D / 128, D, D);
    }

    // 3. flash attention -> fp16 (attn_out + alpha*normed)
    flash_attn<<<dim3(S / 128, H), 256, FL_SMEM>>>(
        qh, kh, vh, normed, alpha, act);

    // 4. x1 = x + attn @ Wo^T * so
    {
        GemmSegs p = {};
        p.B[0] = wo;
        p.Cf = x1; p.R = x;
        p.scale[0] = so; p.sconst[0] = 1.0f;
        mma_gemm<<<dim3(D / 128, S / 128), 256, MMA_SMEM>>>(
            act, p, D / 128, D, D);
    }

    // 5. mlp norm (fused fp16)
    rmsnorm_h_kernel<<<S, 256>>>(x1, wn_m, normed, act);

    // 6. gate + up fused: 2 segments, grid (128, 16)
    {
        GemmSegs p = {};
        p.B[0] = wg; p.B[1] = wu;
        p.Ch[0] = gateh; p.Ch[1] = uph;
        p.scale[0] = sg; p.scale[1] = su;
        p.sconst[0] = 1.0f; p.sconst[1] = 1.0f;
        mma_gemm<<<dim3(2 * DFF / 128, S / 128), 256, MMA_SMEM>>>(
            act, p, DFF / 128, D, DFF);
    }

    // 7. silu*up (fp16 in) -> fp16
    silu_mul_h_kernel<<<(S * DFF / 4) / 256, 256>>>(gateh, uph, act);

    // 8. out = x1 + h @ Wd^T * sd
    {
        GemmSegs p = {};
        p.B[0] = wd;
        p.Cf = out; p.R = x1;
        p.scale[0] = sd; p.sconst[0] = 1.0f;
        mma_gemm<<<dim3(D / 128, S / 128), 256, MMA_SMEM>>>(
            act, p, DFF / 128, DFF, D);
    }
}

// round 14
// speedup vs baseline: 1.0122x; 1.0122x over previous
#include <cuda_runtime.h>
#include <cuda_fp16.h>
#include <cstdint>
#include <math.h>

#define S   2048
#define D   2048
#define DFF 8192
#define H   16
#define DH  128

// ---------------------------------------------------------------------------
// Scratch (device globals; no allocation allowed)
// ---------------------------------------------------------------------------
__device__ float g_normed[(size_t)S * D];
__device__ float g_x1[(size_t)S * D];

__device__ __half g_qh[(size_t)S * D];
__device__ __half g_kh[(size_t)S * D];
__device__ __half g_vh[(size_t)S * D];
__device__ __half g_gate_h[(size_t)S * DFF];
__device__ __half g_up_h[(size_t)S * DFF];

__device__ __half g_wq_h[(size_t)D * D];
__device__ __half g_wk_h[(size_t)D * D];
__device__ __half g_wv_h[(size_t)D * D];
__device__ __half g_wo_h[(size_t)D * D];
__device__ __half g_wg_h[(size_t)DFF * D];
__device__ __half g_wu_h[(size_t)DFF * D];
__device__ __half g_wd_h[(size_t)D * DFF];
__device__ __half g_act[(size_t)S * DFF];      // fp16 activations (max size)

// ---------------------------------------------------------------------------
// helpers
// ---------------------------------------------------------------------------
__device__ __forceinline__ uint32_t smem_u32(const void* p) {
    uint32_t a;
    asm("{ .reg .u64 t; cvta.to.shared.u64 t, %1; cvt.u32.u64 %0, t; }"
        : "=r"(a) : "l"(p));
    return a;
}

__device__ __forceinline__ uint32_t packh(float x, float y) {
    __half2 t = __floats2half2_rn(x, y);
    return *(uint32_t*)&t;
}

__device__ __forceinline__ void mma16816h(float* c, const uint32_t* a,
                                          uint32_t b0, uint32_t b1) {
    asm volatile(
        "mma.sync.aligned.m16n8k16.row.col.f32.f16.f16.f32 "
        "{%0,%1,%2,%3}, {%4,%5,%6,%7}, {%8,%9}, {%0,%1,%2,%3};"
        : "+f"(c[0]), "+f"(c[1]), "+f"(c[2]), "+f"(c[3])
        : "r"(a[0]), "r"(a[1]), "r"(a[2]), "r"(a[3]), "r"(b0), "r"(b1));
}

// ---------------------------------------------------------------------------
// Segmented weight GEMM via mma.sync (fp16 in, fp32 accum).  FROZEN CONFIG.
// CTA 128x128, BK=32, 8 warps (2x4), warp tile 64x32, 3-stage cp.async,
// stage 16KB (48KB total, 2 CTA/SM). Up to 3 segments per launch.
// ---------------------------------------------------------------------------
#define TILE_B   8192
#define STAGE_B  (2 * TILE_B)
#define MMA_SMEM (3 * STAGE_B)

struct GemmSegs {
    const __half* B[3];
    __half*       Ch[3];
    const float*  scale[3];
    float         sconst[3];
    float*        Cf;
    const float*  R;
};

__device__ __forceinline__ uint32_t sw_addr(uint32_t s_tile, int row, int ck) {
    return s_tile + row * 64 + ((ck ^ ((row >> 1) & 3)) << 4);
}

__device__ __forceinline__ void cp_tile(
    uint32_t s_tile, const __half* __restrict__ g,
    int row0, int ld, int k0, int tid)
{
#pragma unroll
    for (int i = 0; i < 2; i++) {
        const int idx = tid + i * 256;
        const int r   = idx >> 2;
        const int ck  = idx & 3;
        const void* src = g + (size_t)(row0 + r) * ld + k0 + ck * 8;
        const uint32_t dst = s_tile + r * 64 + (((ck ^ ((r >> 1) & 3))) << 4);
        asm volatile("cp.async.cg.shared.global [%0], [%1], 16;"
                     :: "r"(dst), "l"(src));
    }
}

__device__ __forceinline__ void load_stage(
    uint32_t stg, const __half* A, const __half* Bw,
    int rowA0, int rowB0, int Ktot, int k0, int tid)
{
    cp_tile(stg,          A,  rowA0, Ktot, k0, tid);
    cp_tile(stg + TILE_B, Bw, rowB0, Ktot, k0, tid);
    asm volatile("cp.async.commit_group;");
}

__global__ __launch_bounds__(256)
void mma_gemm(const __half* __restrict__ A,
              GemmSegs p, int nbn_seg, int Ktot, int ldc)
{
    extern __shared__ char smem[];
    const uint32_t sbase = smem_u32(smem);
    const int tid = threadIdx.x;
    const int l   = tid & 31;
    const int w   = tid >> 5;
    const int wm  = w >> 2;
    const int wn  = w & 3;
    const int bm  = blockIdx.y;
    const int seg = blockIdx.x / nbn_seg;
    const int bnl = blockIdx.x % nbn_seg;
    const int rowA0 = bm * 128;
    const int rowB0 = bnl * 128;
    const __half* Bw = p.B[seg];

    float acc[4][4][4];
#pragma unroll
    for (int i = 0; i < 4; i++)
#pragma unroll
        for (int j = 0; j < 4; j++)
#pragma unroll
            for (int c = 0; c < 4; c++) acc[i][j][c] = 0.0f;

    const int nc = Ktot >> 5;

    load_stage(sbase,           A, Bw, rowA0, rowB0, Ktot, 0,  tid);
    load_stage(sbase + STAGE_B, A, Bw, rowA0, rowB0, Ktot, 32, tid);

    for (int c = 0; c < nc; c++) {
        if (c + 2 < nc) {
            load_stage(sbase + ((c + 2) % 3) * STAGE_B, A, Bw,
                       rowA0, rowB0, Ktot, (c + 2) * 32, tid);
            asm volatile("cp.async.wait_group 2;");
        } else if (c + 1 < nc) {
            asm volatile("cp.async.wait_group 1;");
        } else {
            asm volatile("cp.async.wait_group 0;");
        }
        __syncthreads();

        const uint32_t st = sbase + (c % 3) * STAGE_B;
        const uint32_t sA = st;
        const uint32_t sB = st + TILE_B;

#pragma unroll
        for (int ks = 0; ks < 2; ks++) {
            uint32_t bf[4][2];
#pragma unroll
            for (int nf = 0; nf < 4; nf++) {
                const int nrow = wn * 32 + nf * 8 + (l & 7);
                const int ck   = ks * 2 + ((l >> 3) & 1);
                asm volatile(
                    "ldmatrix.sync.aligned.m8n8.x2.shared.b16 {%0,%1}, [%2];"
                    : "=r"(bf[nf][0]), "=r"(bf[nf][1])
                    : "r"(sw_addr(sB, nrow, ck)));
            }
            uint32_t af[4][4];
#pragma unroll
            for (int mf = 0; mf < 4; mf++) {
                const int arow = wm * 64 + mf * 16 + (l & 15);
                const int ck   = ks * 2 + (l >> 4);
                asm volatile(
                    "ldmatrix.sync.aligned.m8n8.x4.shared.b16 {%0,%1,%2,%3}, [%4];"
                    : "=r"(af[mf][0]), "=r"(af[mf][1]),
                      "=r"(af[mf][2]), "=r"(af[mf][3])
                    : "r"(sw_addr(sA, arow, ck)));
            }
#pragma unroll
            for (int mf = 0; mf < 4; mf++)
#pragma unroll
                for (int nf = 0; nf < 4; nf++)
                    mma16816h(acc[mf][nf], af[mf], bf[nf][0], bf[nf][1]);
        }
        __syncthreads();
    }

    float sc = p.sconst[seg];
    if (p.scale[seg]) sc *= __ldg(p.scale[seg]);
    __half* Ch = p.Ch[seg];
    const int qrow = l >> 2;
    const int qcol = (l & 3) * 2;

#pragma unroll
    for (int mf = 0; mf < 4; mf++) {
        const size_t r0 = (size_t)(bm * 128 + wm * 64 + mf * 16 + qrow);
#pragma unroll
        for (int nf = 0; nf < 4; nf++) {
            const size_t c0 = (size_t)(bnl * 128 + wn * 32 + nf * 8 + qcol);
#pragma unroll
            for (int half = 0; half < 2; half++) {
                const size_t row = r0 + half * 8;
                const size_t off = row * ldc + c0;
                float ox = acc[mf][nf][half * 2 + 0] * sc;
                float oy = acc[mf][nf][half * 2 + 1] * sc;
                if (Ch) {
                    *(uint32_t*)(Ch + off) = packh(ox, oy);
                } else {
                    if (p.R) {
                        const float2 rv = *(const float2*)(p.R + off);
                        ox += rv.x; oy += rv.y;
                    }
                    float2 o; o.x = ox; o.y = oy;
                    *(float2*)(p.Cf + off) = o;
                }
            }
        }
    }
}

// ---------------------------------------------------------------------------
// Flash attention (fp16 tensor cores, fp32 online softmax).
// Round-12 body (Q in registers, overlapped KV double-buffer) + LJF remap:
// bq = gridDim.x-1-blockIdx.x so heavy causal tiles are scheduled first.
// ---------------------------------------------------------------------------
#define FL_STAGE 65536
#define FL_SMEM  (2 * FL_STAGE)

__device__ __forceinline__ uint32_t sw256(uint32_t base, int row, int ck) {
    return base + row * 256 + (((((ck & 7) ^ (row & 7))) | (ck & 8)) << 4);
}

__device__ __forceinline__ void cp_tile256(
    uint32_t s_tile, const __half* __restrict__ g,
    int row0, int col0, int tid)
{
#pragma unroll
    for (int i = 0; i < 8; i++) {
        const int idx = tid + i * 256;
        const int r  = idx >> 4;
        const int ck = idx & 15;
        const void* src = g + (size_t)(row0 + r) * D + col0 + ck * 8;
        asm volatile("cp.async.cg.shared.global [%0], [%1], 16;"
                     :: "r"(sw256(s_tile, r, ck)), "l"(src));
    }
}

__global__ __launch_bounds__(256)
void flash_attn(const __half* __restrict__ Qh,
                const __half* __restrict__ Kh,
                const __half* __restrict__ Vh,
                const float* __restrict__ normed,
                const float* __restrict__ alpha,
                __half* __restrict__ outh)
{
    extern __shared__ char smem[];
    const uint32_t sbase = smem_u32(smem);
    const int tid = threadIdx.x;
    const int l   = tid & 31;
    const int w   = tid >> 5;
    // longest-job-first: largest bq (most KV blocks) scheduled first
    const int bq  = (int)gridDim.x - 1 - (int)blockIdx.x;
    const int h   = blockIdx.y;
    const int col0 = h * DH;

    cp_tile256(sbase, Qh, bq * 128, col0, tid);
    asm volatile("cp.async.commit_group;");
    asm volatile("cp.async.wait_group 0;");
    __syncthreads();

    uint32_t qf[8][4];
#pragma unroll
    for (int kk = 0; kk < 8; kk++) {
        const int r  = w * 16 + (l & 15);
        const int ck = kk * 2 + (l >> 4);
        asm volatile("ldmatrix.sync.aligned.m8n8.x4.shared.b16 {%0,%1,%2,%3}, [%4];"
            : "=r"(qf[kk][0]), "=r"(qf[kk][1]), "=r"(qf[kk][2]), "=r"(qf[kk][3])
            : "r"(sw256(sbase, r, ck)));
    }
    __syncthreads();

    float oacc[16][4];
#pragma unroll
    for (int i = 0; i < 16; i++)
#pragma unroll
        for (int j = 0; j < 4; j++) oacc[i][j] = 0.0f;
    float m0 = -1e30f, m1 = -1e30f, l0 = 0.0f, l1 = 0.0f;

    cp_tile256(sbase,         Kh, 0, col0, tid);
    cp_tile256(sbase + 32768, Vh, 0, col0, tid);
    asm volatile("cp.async.commit_group;");

    for (int kb = 0; kb <= bq; kb++) {
        if (kb + 1 <= bq) {
            const uint32_t nb = sbase + ((kb + 1) & 1) * FL_STAGE;
            cp_tile256(nb,         Kh, (kb + 1) * 128, col0, tid);
            cp_tile256(nb + 32768, Vh, (kb + 1) * 128, col0, tid);
            asm volatile("cp.async.commit_group;");
            asm volatile("cp.async.wait_group 1;");
        } else {
            asm volatile("cp.async.wait_group 0;");
        }
        __syncthreads();

        const uint32_t sK = sbase + (kb & 1) * FL_STAGE;
        const uint32_t sV = sK + 32768;

        float sacc[16][4];
#pragma unroll
        for (int i = 0; i < 16; i++)
#pragma unroll
            for (int j = 0; j < 4; j++) sacc[i][j] = 0.0f;

#pragma unroll
        for (int kk = 0; kk < 8; kk++) {
#pragma unroll
            for (int p = 0; p < 8; p++) {
                uint32_t b[4];
                const int r  = p * 16 + ((l >> 4) << 3) + (l & 7);
                const int ck = kk * 2 + ((l >> 3) & 1);
                asm volatile(
                    "ldmatrix.sync.aligned.m8n8.x4.shared.b16 {%0,%1,%2,%3}, [%4];"
                    : "=r"(b[0]), "=r"(b[1]), "=r"(b[2]), "=r"(b[3])
                    : "r"(sw256(sK, r, ck)));
                mma16816h(sacc[2 * p],     qf[kk], b[0], b[1]);
                mma16816h(sacc[2 * p + 1], qf[kk], b[2], b[3]);
            }
        }

        if (kb == bq) {
            const int r0 = w * 16 + (l >> 2);
#pragma unroll
            for (int nf = 0; nf < 16; nf++) {
                const int c0 = nf * 8 + (l & 3) * 2;
                if (c0     > r0)     sacc[nf][0] = -1e30f;
                if (c0 + 1 > r0)     sacc[nf][1] = -1e30f;
                if (c0     > r0 + 8) sacc[nf][2] = -1e30f;
                if (c0 + 1 > r0 + 8) sacc[nf][3] = -1e30f;
            }
        }

        float bm0 = -1e30f, bm1 = -1e30f;
#pragma unroll
        for (int nf = 0; nf < 16; nf++) {
            bm0 = fmaxf(bm0, fmaxf(sacc[nf][0], sacc[nf][1]));
            bm1 = fmaxf(bm1, fmaxf(sacc[nf][2], sacc[nf][3]));
        }
        bm0 = fmaxf(bm0, __shfl_xor_sync(0xFFFFFFFFu, bm0, 1));
        bm0 = fmaxf(bm0, __shfl_xor_sync(0xFFFFFFFFu, bm0, 2));
        bm1 = fmaxf(bm1, __shfl_xor_sync(0xFFFFFFFFu, bm1, 1));
        bm1 = fmaxf(bm1, __shfl_xor_sync(0xFFFFFFFFu, bm1, 2));

        const float nm0 = fmaxf(m0, bm0);
        const float nm1 = fmaxf(m1, bm1);
        const float sf0 = __expf(m0 - nm0);
        const float sf1 = __expf(m1 - nm1);

        float rs0 = 0.0f, rs1 = 0.0f;
#pragma unroll
        for (int nf = 0; nf < 16; nf++) {
            const float p0 = __expf(sacc[nf][0] - nm0);
            const float p1 = __expf(sacc[nf][1] - nm0);
            const float p2 = __expf(sacc[nf][2] - nm1);
            const float p3 = __expf(sacc[nf][3] - nm1);
            sacc[nf][0] = p0; sacc[nf][1] = p1;
            sacc[nf][2] = p2; sacc[nf][3] = p3;
            rs0 += p0 + p1; rs1 += p2 + p3;
        }
        rs0 += __shfl_xor_sync(0xFFFFFFFFu, rs0, 1);
        rs0 += __shfl_xor_sync(0xFFFFFFFFu, rs0, 2);
        rs1 += __shfl_xor_sync(0xFFFFFFFFu, rs1, 1);
        rs1 += __shfl_xor_sync(0xFFFFFFFFu, rs1, 2);

        l0 = l0 * sf0 + rs0;
        l1 = l1 * sf1 + rs1;
        m0 = nm0; m1 = nm1;
#pragma unroll
        for (int nf = 0; nf < 16; nf++) {
            oacc[nf][0] *= sf0; oacc[nf][1] *= sf0;
            oacc[nf][2] *= sf1; oacc[nf][3] *= sf1;
        }

#pragma unroll
        for (int kk = 0; kk < 8; kk++) {
            uint32_t a[4];
            a[0] = packh(sacc[2 * kk][0],     sacc[2 * kk][1]);
            a[1] = packh(sacc[2 * kk][2],     sacc[2 * kk][3]);
            a[2] = packh(sacc[2 * kk + 1][0], sacc[2 * kk + 1][1]);
            a[3] = packh(sacc[2 * kk + 1][2], sacc[2 * kk + 1][3]);
#pragma unroll
            for (int p = 0; p < 8; p++) {
                uint32_t b[4];
                const int r  = kk * 16 + ((l >> 3) & 1) * 8 + (l & 7);
                const int ck = 2 * p + (l >> 4);
                asm volatile(
                    "ldmatrix.sync.aligned.m8n8.x4.trans.shared.b16 {%0,%1,%2,%3}, [%4];"
                    : "=r"(b[0]), "=r"(b[1]), "=r"(b[2]), "=r"(b[3])
                    : "r"(sw256(sV, r, ck)));
                mma16816h(oacc[2 * p],     a, b[0], b[1]);
                mma16816h(oacc[2 * p + 1], a, b[2], b[3]);
            }
        }
        __syncthreads();
    }

    const float il0 = 1.0f / l0;
    const float il1 = 1.0f / l1;
    const float al  = __ldg(alpha + h);
    const size_t r0g = (size_t)(bq * 128 + w * 16 + (l >> 2));
    const size_t r1g = r0g + 8;

#pragma unroll
    for (int nf = 0; nf < 16; nf++) {
        const size_t cg = (size_t)(col0 + nf * 8 + (l & 3) * 2);
#pragma unroll
        for (int rr = 0; rr < 2; rr++) {
            const size_t row = rr ? r1g : r0g;
            const float il = rr ? il1 : il0;
            const float v0 = oacc[nf][rr * 2 + 0] * il + al * normed[row * D + cg];
            const float v1 = oacc[nf][rr * 2 + 1] * il + al * normed[row * D + cg + 1];
            *(uint32_t*)(outh + row * D + cg) = packh(v0, v1);
        }
    }
}

// ---------------------------------------------------------------------------
// Fused weight conversion: all 7 weights in one launch.
// ---------------------------------------------------------------------------
struct CvtParams {
    const float* src[7];
    __half*      dst[7];
    int          start[8];
};

__global__ __launch_bounds__(256) void convert_all_kernel(CvtParams p)
{
    const int b = blockIdx.x;
    int seg = 0;
#pragma unroll
    for (int s = 1; s < 7; s++)
        if (b >= p.start[s]) seg = s;
    const int i = (b - p.start[seg]) * 256 + threadIdx.x;
    const float4 v0 = ((const float4*)p.src[seg])[2 * i];
    const float4 v1 = ((const float4*)p.src[seg])[2 * i + 1];
    uint4 o;
    o.x = packh(v0.x, v0.y);
    o.y = packh(v0.z, v0.w);
    o.z = packh(v1.x, v1.y);
    o.w = packh(v1.z, v1.w);
    ((uint4*)p.dst[seg])[i] = o;
}

// rmsnorm -> f32 out + fp16 out, one block per row
__global__ __launch_bounds__(256) void rmsnorm_h_kernel(
    const float* __restrict__ x, const float* __restrict__ w,
    float* __restrict__ outf, __half* __restrict__ outh)
{
    __shared__ float red[256];
    const int r = blockIdx.x;
    const int tid = threadIdx.x;
    const float* xr = x + (size_t)r * D;

    float ss = 0.0f;
#pragma unroll
    for (int j4 = tid; j4 < D / 4; j4 += 256) {
        const float4 v = ((const float4*)xr)[j4];
        ss += v.x * v.x + v.y * v.y + v.z * v.z + v.w * v.w;
    }
    red[tid] = ss;
    __syncthreads();
    for (int s = 128; s > 0; s >>= 1) {
        if (tid < s) red[tid] += red[tid + s];
        __syncthreads();
    }
    const float sc = rsqrtf(red[0] / (float)D + 1e-6f);

#pragma unroll
    for (int j4 = tid; j4 < D / 4; j4 += 256) {
        const float4 v  = ((const float4*)xr)[j4];
        const float4 wv = ((const float4*)w)[j4];
        const float o0 = v.x * sc * wv.x;
        const float o1 = v.y * sc * wv.y;
        const float o2 = v.z * sc * wv.z;
        const float o3 = v.w * sc * wv.w;
        float4 of; of.x = o0; of.y = o1; of.z = o2; of.w = o3;
        ((float4*)(outf + (size_t)r * D))[j4] = of;
        uint2 oh;
        oh.x = packh(o0, o1);
        oh.y = packh(o2, o3);
        ((uint2*)(outh + (size_t)r * D))[j4] = oh;
    }
}

// h = silu(g)*u with fp16 g,u inputs -> fp16 out
__global__ __launch_bounds__(256) void silu_mul_h_kernel(
    const __half* __restrict__ g, const __half* __restrict__ u,
    __half* __restrict__ outh)
{
    const size_t i = (size_t)blockIdx.x * 256 + threadIdx.x;
    const uint2 gv = ((const uint2*)g)[i];
    const uint2 uv = ((const uint2*)u)[i];
    const __half2 g0 = *(const __half2*)&gv.x;
    const __half2 g1 = *(const __half2*)&gv.y;
    const __half2 u0 = *(const __half2*)&uv.x;
    const __half2 u1 = *(const __half2*)&uv.y;
    const float gx = __half2float(g0.x), gy = __half2float(g0.y);
    const float gz = __half2float(g1.x), gw = __half2float(g1.y);
    const float a0 = gx / (1.0f + __expf(-gx)) * __half2float(u0.x);
    const float a1 = gy / (1.0f + __expf(-gy)) * __half2float(u0.y);
    const float a2 = gz / (1.0f + __expf(-gz)) * __half2float(u1.x);
    const float a3 = gw / (1.0f + __expf(-gw)) * __half2float(u1.y);
    uint2 o;
    o.x = packh(a0, a1);
    o.y = packh(a2, a3);
    ((uint2*)outh)[i] = o;
}

// ---------------------------------------------------------------------------
// Launch
// ---------------------------------------------------------------------------
extern "C" void kernel_launch(void* const* d_in, const int* in_sizes, int n_in,
                              void* d_out, int out_size)
{
    (void)in_sizes; (void)n_in; (void)out_size;

    const float* x     = (const float*)d_in[0];
    const float* wn_a  = (const float*)d_in[1];
    const float* wn_m  = (const float*)d_in[2];
    const float* Wq    = (const float*)d_in[3];
    const float* sq    = (const float*)d_in[4];
    const float* Wk    = (const float*)d_in[5];
    const float* sk    = (const float*)d_in[6];
    const float* Wv    = (const float*)d_in[7];
    const float* sv    = (const float*)d_in[8];
    const float* Wo    = (const float*)d_in[9];
    const float* so    = (const float*)d_in[10];
    const float* Wg    = (const float*)d_in[11];
    const float* sg    = (const float*)d_in[12];
    const float* Wu    = (const float*)d_in[13];
    const float* su    = (const float*)d_in[14];
    const float* Wd    = (const float*)d_in[15];
    const float* sd    = (const float*)d_in[16];
    const float* alpha = (const float*)d_in[17];
    float* out = (float*)d_out;

    float *normed, *x1;
    cudaGetSymbolAddress((void**)&normed, g_normed);
    cudaGetSymbolAddress((void**)&x1,     g_x1);

    __half *qh, *kh, *vh, *gateh, *uph, *wq, *wk, *wv, *wo, *wg, *wu, *wd, *act;
    cudaGetSymbolAddress((void**)&qh, g_qh);
    cudaGetSymbolAddress((void**)&kh, g_kh);
    cudaGetSymbolAddress((void**)&vh, g_vh);
    cudaGetSymbolAddress((void**)&gateh, g_gate_h);
    cudaGetSymbolAddress((void**)&uph,   g_up_h);
    cudaGetSymbolAddress((void**)&wq, g_wq_h);
    cudaGetSymbolAddress((void**)&wk, g_wk_h);
    cudaGetSymbolAddress((void**)&wv, g_wv_h);
    cudaGetSymbolAddress((void**)&wo, g_wo_h);
    cudaGetSymbolAddress((void**)&wg, g_wg_h);
    cudaGetSymbolAddress((void**)&wu, g_wu_h);
    cudaGetSymbolAddress((void**)&wd, g_wd_h);
    cudaGetSymbolAddress((void**)&act, g_act);

    cudaFuncSetAttribute(mma_gemm, cudaFuncAttributeMaxDynamicSharedMemorySize,
                         MMA_SMEM);
    cudaFuncSetAttribute(flash_attn, cudaFuncAttributeMaxDynamicSharedMemorySize,
                         FL_SMEM);

    const float inv_sqrt_dh = 0.08838834764831845f;  // 1/sqrt(128)

    // 0. all weights -> fp16 in one launch (exact for ternary)
    const int bDD = D * D / 8 / 256;
    const int bFD = DFF * D / 8 / 256;
    CvtParams cp;
    cp.src[0] = Wq; cp.dst[0] = wq;
    cp.src[1] = Wk; cp.dst[1] = wk;
    cp.src[2] = Wv; cp.dst[2] = wv;
    cp.src[3] = Wo; cp.dst[3] = wo;
    cp.src[4] = Wg; cp.dst[4] = wg;
    cp.src[5] = Wu; cp.dst[5] = wu;
    cp.src[6] = Wd; cp.dst[6] = wd;
    cp.start[0] = 0;
    cp.start[1] = bDD;
    cp.start[2] = 2 * bDD;
    cp.start[3] = 3 * bDD;
    cp.start[4] = 4 * bDD;
    cp.start[5] = 4 * bDD + bFD;
    cp.start[6] = 4 * bDD + 2 * bFD;
    cp.start[7] = 4 * bDD + 3 * bFD;
    convert_all_kernel<<<cp.start[7], 256>>>(cp);

    // 1. rmsnorm (f32 + fp16 fused)
    rmsnorm_h_kernel<<<S, 256>>>(x, wn_a, normed, act);

    // 2. QKV fused: 3 segments, grid (48, 16)
    {
        GemmSegs p = {};
        p.B[0] = wq; p.B[1] = wk; p.B[2] = wv;
        p.Ch[0] = qh; p.Ch[1] = kh; p.Ch[2] = vh;
        p.scale[0] = sq; p.scale[1] = sk; p.scale[2] = sv;
        p.sconst[0] = inv_sqrt_dh; p.sconst[1] = 1.0f; p.sconst[2] = 1.0f;
        mma_gemm<<<dim3(3 * D / 128, S / 128), 256, MMA_SMEM>>>(
            act, p, D / 128, D, D);
    }

    // 3. flash attention -> fp16 (attn_out + alpha*normed)
    flash_attn<<<dim3(S / 128, H), 256, FL_SMEM>>>(
        qh, kh, vh, normed, alpha, act);

    // 4. x1 = x + attn @ Wo^T * so
    {
        GemmSegs p = {};
        p.B[0] = wo;
        p.Cf = x1; p.R = x;
        p.scale[0] = so; p.sconst[0] = 1.0f;
        mma_gemm<<<dim3(D / 128, S / 128), 256, MMA_SMEM>>>(
            act, p, D / 128, D, D);
    }

    // 5. mlp norm (fused fp16)
    rmsnorm_h_kernel<<<S, 256>>>(x1, wn_m, normed, act);

    // 6. gate + up fused: 2 segments, grid (128, 16)
    {
        GemmSegs p = {};
        p.B[0] = wg; p.B[1] = wu;
        p.Ch[0] = gateh; p.Ch[1] = uph;
        p.scale[0] = sg; p.scale[1] = su;
        p.sconst[0] = 1.0f; p.sconst[1] = 1.0f;
        mma_gemm<<<dim3(2 * DFF / 128, S / 128), 256, MMA_SMEM>>>(
            act, p, DFF / 128, D, DFF);
    }

    // 7. silu*up (fp16 in) -> fp16
    silu_mul_h_kernel<<<(S * DFF / 4) / 256, 256>>>(gateh, uph, act);

    // 8. out = x1 + h @ Wd^T * sd
    {
        GemmSegs p = {};
        p.B[0] = wd;
        p.Cf = out; p.R = x1;
        p.scale[0] = sd; p.sconst[0] = 1.0f;
        mma_gemm<<<dim3(D / 128, S / 128), 256, MMA_SMEM>>>(
            act, p, DFF / 128, DFF, D);
    }
}

// round 16
// speedup vs baseline: 1.0890x; 1.0759x over previous
#include <cuda_runtime.h>
#include <cuda_fp16.h>
#include <cstdint>
#include <math.h>

#define S   2048
#define D   2048
#define DFF 8192
#define H   16
#define DH  128

// ---------------------------------------------------------------------------
// Scratch (device globals; no allocation allowed)
// ---------------------------------------------------------------------------
__device__ float g_normed[(size_t)S * D];
__device__ float g_x1[(size_t)S * D];

__device__ __half g_qh[(size_t)S * D];
__device__ __half g_kh[(size_t)S * D];
__device__ __half g_vh[(size_t)S * D];
__device__ __half g_gate_h[(size_t)S * DFF];
__device__ __half g_up_h[(size_t)S * DFF];

__device__ __half g_wq_h[(size_t)D * D];
__device__ __half g_wk_h[(size_t)D * D];
__device__ __half g_wv_h[(size_t)D * D];
__device__ __half g_wo_h[(size_t)D * D];
__device__ __half g_wg_h[(size_t)DFF * D];
__device__ __half g_wu_h[(size_t)DFF * D];
__device__ __half g_wd_h[(size_t)D * DFF];
__device__ __half g_act[(size_t)S * DFF];      // fp16 activations (max size)

// ---------------------------------------------------------------------------
// helpers
// ---------------------------------------------------------------------------
__device__ __forceinline__ uint32_t smem_u32(const void* p) {
    uint32_t a;
    asm("{ .reg .u64 t; cvta.to.shared.u64 t, %1; cvt.u32.u64 %0, t; }"
        : "=r"(a) : "l"(p));
    return a;
}

__device__ __forceinline__ uint32_t packh(float x, float y) {
    __half2 t = __floats2half2_rn(x, y);
    return *(uint32_t*)&t;
}

__device__ __forceinline__ void mma16816h(float* c, const uint32_t* a,
                                          uint32_t b0, uint32_t b1) {
    asm volatile(
        "mma.sync.aligned.m16n8k16.row.col.f32.f16.f16.f32 "
        "{%0,%1,%2,%3}, {%4,%5,%6,%7}, {%8,%9}, {%0,%1,%2,%3};"
        : "+f"(c[0]), "+f"(c[1]), "+f"(c[2]), "+f"(c[3])
        : "r"(a[0]), "r"(a[1]), "r"(a[2]), "r"(a[3]), "r"(b0), "r"(b1));
}

// ---------------------------------------------------------------------------
// Segmented weight GEMM via mma.sync (fp16 in, fp32 accum).
// Round-15/16: CTA tile 128x128 (grids unchanged), but 4 warps (128 threads)
// with warp tile 64x64 (2x2 warp grid). Same BK=32, 3-stage cp.async,
// stage 16KB (48KB). 2 CTA/SM (256 thr, 96KB smem) = 8 warps/SM as before,
// with a better mma/ldmatrix ratio (32/12 vs 16/8) per warp.
// ---------------------------------------------------------------------------
#define TILE_B   8192
#define STAGE_B  (2 * TILE_B)
#define MMA_SMEM (3 * STAGE_B)

struct GemmSegs {
    const __half* B[3];
    __half*       Ch[3];
    const float*  scale[3];
    float         sconst[3];
    float*        Cf;
    const float*  R;
};

__device__ __forceinline__ uint32_t sw_addr(uint32_t s_tile, int row, int ck) {
    return s_tile + row * 64 + ((ck ^ ((row >> 1) & 3)) << 4);
}

// 128 threads: 512 16B chunks per tile -> 4 iterations
__device__ __forceinline__ void cp_tile(
    uint32_t s_tile, const __half* __restrict__ g,
    int row0, int ld, int k0, int tid)
{
#pragma unroll
    for (int i = 0; i < 4; i++) {
        const int idx = tid + i * 128;      // 0..511
        const int r   = idx >> 2;           // row 0..127
        const int ck  = idx & 3;            // 16B chunk 0..3
        const void* src = g + (size_t)(row0 + r) * ld + k0 + ck * 8;
        const uint32_t dst = s_tile + r * 64 + (((ck ^ ((r >> 1) & 3))) << 4);
        asm volatile("cp.async.cg.shared.global [%0], [%1], 16;"
                     :: "r"(dst), "l"(src));
    }
}

__device__ __forceinline__ void load_stage(
    uint32_t stg, const __half* A, const __half* Bw,
    int rowA0, int rowB0, int Ktot, int k0, int tid)
{
    cp_tile(stg,          A,  rowA0, Ktot, k0, tid);
    cp_tile(stg + TILE_B, Bw, rowB0, Ktot, k0, tid);
    asm volatile("cp.async.commit_group;");
}

__global__ __launch_bounds__(128)
void mma_gemm(const __half* __restrict__ A,
              GemmSegs p, int nbn_seg, int Ktot, int ldc)
{
    extern __shared__ char smem[];
    const uint32_t sbase = smem_u32(smem);
    const int tid = threadIdx.x;
    const int l   = tid & 31;
    const int w   = tid >> 5;          // 0..3
    const int wm  = w >> 1;            // 0..1  (64-row slab)
    const int wn  = w & 1;             // 0..1  (64-col slab)
    const int bm  = blockIdx.y;
    const int seg = blockIdx.x / nbn_seg;
    const int bnl = blockIdx.x % nbn_seg;
    const int rowA0 = bm * 128;
    const int rowB0 = bnl * 128;
    const __half* Bw = p.B[seg];

    float acc[4][8][4];
#pragma unroll
    for (int i = 0; i < 4; i++)
#pragma unroll
        for (int j = 0; j < 8; j++)
#pragma unroll
            for (int c = 0; c < 4; c++) acc[i][j][c] = 0.0f;

    const int nc = Ktot >> 5;

    load_stage(sbase,           A, Bw, rowA0, rowB0, Ktot, 0,  tid);
    load_stage(sbase + STAGE_B, A, Bw, rowA0, rowB0, Ktot, 32, tid);

    for (int c = 0; c < nc; c++) {
        if (c + 2 < nc) {
            load_stage(sbase + ((c + 2) % 3) * STAGE_B, A, Bw,
                       rowA0, rowB0, Ktot, (c + 2) * 32, tid);
            asm volatile("cp.async.wait_group 2;");
        } else if (c + 1 < nc) {
            asm volatile("cp.async.wait_group 1;");
        } else {
            asm volatile("cp.async.wait_group 0;");
        }
        __syncthreads();

        const uint32_t st = sbase + (c % 3) * STAGE_B;
        const uint32_t sA = st;
        const uint32_t sB = st + TILE_B;

#pragma unroll
        for (int ks = 0; ks < 2; ks++) {
            uint32_t bf[8][2];
#pragma unroll
            for (int nf = 0; nf < 8; nf++) {
                const int nrow = wn * 64 + nf * 8 + (l & 7);
                const int ck   = ks * 2 + ((l >> 3) & 1);
                asm volatile(
                    "ldmatrix.sync.aligned.m8n8.x2.shared.b16 {%0,%1}, [%2];"
                    : "=r"(bf[nf][0]), "=r"(bf[nf][1])
                    : "r"(sw_addr(sB, nrow, ck)));
            }
#pragma unroll
            for (int mf = 0; mf < 4; mf++) {
                uint32_t af[4];
                const int arow = wm * 64 + mf * 16 + (l & 15);
                const int ck   = ks * 2 + (l >> 4);
                asm volatile(
                    "ldmatrix.sync.aligned.m8n8.x4.shared.b16 {%0,%1,%2,%3}, [%4];"
                    : "=r"(af[0]), "=r"(af[1]), "=r"(af[2]), "=r"(af[3])
                    : "r"(sw_addr(sA, arow, ck)));
#pragma unroll
                for (int nf = 0; nf < 8; nf++)
                    mma16816h(acc[mf][nf], af, bf[nf][0], bf[nf][1]);
            }
        }
        __syncthreads();
    }

    float sc = p.sconst[seg];
    if (p.scale[seg]) sc *= __ldg(p.scale[seg]);
    __half* Ch = p.Ch[seg];
    const int qrow = l >> 2;
    const int qcol = (l & 3) * 2;

#pragma unroll
    for (int mf = 0; mf < 4; mf++) {
        const size_t r0 = (size_t)(bm * 128 + wm * 64 + mf * 16 + qrow);
#pragma unroll
        for (int nf = 0; nf < 8; nf++) {
            const size_t c0 = (size_t)(bnl * 128 + wn * 64 + nf * 8 + qcol);
#pragma unroll
            for (int half = 0; half < 2; half++) {
                const size_t row = r0 + half * 8;
                const size_t off = row * ldc + c0;
                float ox = acc[mf][nf][half * 2 + 0] * sc;
                float oy = acc[mf][nf][half * 2 + 1] * sc;
                if (Ch) {
                    *(uint32_t*)(Ch + off) = packh(ox, oy);
                } else {
                    if (p.R) {
                        const float2 rv = *(const float2*)(p.R + off);
                        ox += rv.x; oy += rv.y;
                    }
                    float2 o; o.x = ox; o.y = oy;
                    *(float2*)(p.Cf + off) = o;
                }
            }
        }
    }
}

// ---------------------------------------------------------------------------
// Flash attention (fp16 tensor cores, fp32 online softmax). UNCHANGED
// (round-12 body + LJF remap).
// ---------------------------------------------------------------------------
#define FL_STAGE 65536
#define FL_SMEM  (2 * FL_STAGE)

__device__ __forceinline__ uint32_t sw256(uint32_t base, int row, int ck) {
    return base + row * 256 + (((((ck & 7) ^ (row & 7))) | (ck & 8)) << 4);
}

__device__ __forceinline__ void cp_tile256(
    uint32_t s_tile, const __half* __restrict__ g,
    int row0, int col0, int tid)
{
#pragma unroll
    for (int i = 0; i < 8; i++) {
        const int idx = tid + i * 256;
        const int r  = idx >> 4;
        const int ck = idx & 15;
        const void* src = g + (size_t)(row0 + r) * D + col0 + ck * 8;
        asm volatile("cp.async.cg.shared.global [%0], [%1], 16;"
                     :: "r"(sw256(s_tile, r, ck)), "l"(src));
    }
}

__global__ __launch_bounds__(256)
void flash_attn(const __half* __restrict__ Qh,
                const __half* __restrict__ Kh,
                const __half* __restrict__ Vh,
                const float* __restrict__ normed,
                const float* __restrict__ alpha,
                __half* __restrict__ outh)
{
    extern __shared__ char smem[];
    const uint32_t sbase = smem_u32(smem);
    const int tid = threadIdx.x;
    const int l   = tid & 31;
    const int w   = tid >> 5;
    const int bq  = (int)gridDim.x - 1 - (int)blockIdx.x;   // LJF
    const int h   = blockIdx.y;
    const int col0 = h * DH;

    cp_tile256(sbase, Qh, bq * 128, col0, tid);
    asm volatile("cp.async.commit_group;");
    asm volatile("cp.async.wait_group 0;");
    __syncthreads();

    uint32_t qf[8][4];
#pragma unroll
    for (int kk = 0; kk < 8; kk++) {
        const int r  = w * 16 + (l & 15);
        const int ck = kk * 2 + (l >> 4);
        asm volatile("ldmatrix.sync.aligned.m8n8.x4.shared.b16 {%0,%1,%2,%3}, [%4];"
            : "=r"(qf[kk][0]), "=r"(qf[kk][1]), "=r"(qf[kk][2]), "=r"(qf[kk][3])
            : "r"(sw256(sbase, r, ck)));
    }
    __syncthreads();

    float oacc[16][4];
#pragma unroll
    for (int i = 0; i < 16; i++)
#pragma unroll
        for (int j = 0; j < 4; j++) oacc[i][j] = 0.0f;
    float m0 = -1e30f, m1 = -1e30f, l0 = 0.0f, l1 = 0.0f;

    cp_tile256(sbase,         Kh, 0, col0, tid);
    cp_tile256(sbase + 32768, Vh, 0, col0, tid);
    asm volatile("cp.async.commit_group;");

    for (int kb = 0; kb <= bq; kb++) {
        if (kb + 1 <= bq) {
            const uint32_t nb = sbase + ((kb + 1) & 1) * FL_STAGE;
            cp_tile256(nb,         Kh, (kb + 1) * 128, col0, tid);
            cp_tile256(nb + 32768, Vh, (kb + 1) * 128, col0, tid);
            asm volatile("cp.async.commit_group;");
            asm volatile("cp.async.wait_group 1;");
        } else {
            asm volatile("cp.async.wait_group 0;");
        }
        __syncthreads();

        const uint32_t sK = sbase + (kb & 1) * FL_STAGE;
        const uint32_t sV = sK + 32768;

        float sacc[16][4];
#pragma unroll
        for (int i = 0; i < 16; i++)
#pragma unroll
            for (int j = 0; j < 4; j++) sacc[i][j] = 0.0f;

#pragma unroll
        for (int kk = 0; kk < 8; kk++) {
#pragma unroll
            for (int p = 0; p < 8; p++) {
                uint32_t b[4];
                const int r  = p * 16 + ((l >> 4) << 3) + (l & 7);
                const int ck = kk * 2 + ((l >> 3) & 1);
                asm volatile(
                    "ldmatrix.sync.aligned.m8n8.x4.shared.b16 {%0,%1,%2,%3}, [%4];"
                    : "=r"(b[0]), "=r"(b[1]), "=r"(b[2]), "=r"(b[3])
                    : "r"(sw256(sK, r, ck)));
                mma16816h(sacc[2 * p],     qf[kk], b[0], b[1]);
                mma16816h(sacc[2 * p + 1], qf[kk], b[2], b[3]);
            }
        }

        if (kb == bq) {
            const int r0 = w * 16 + (l >> 2);
#pragma unroll
            for (int nf = 0; nf < 16; nf++) {
                const int c0 = nf * 8 + (l & 3) * 2;
                if (c0     > r0)     sacc[nf][0] = -1e30f;
                if (c0 + 1 > r0)     sacc[nf][1] = -1e30f;
                if (c0     > r0 + 8) sacc[nf][2] = -1e30f;
                if (c0 + 1 > r0 + 8) sacc[nf][3] = -1e30f;
            }
        }

        float bm0 = -1e30f, bm1 = -1e30f;
#pragma unroll
        for (int nf = 0; nf < 16; nf++) {
            bm0 = fmaxf(bm0, fmaxf(sacc[nf][0], sacc[nf][1]));
            bm1 = fmaxf(bm1, fmaxf(sacc[nf][2], sacc[nf][3]));
        }
        bm0 = fmaxf(bm0, __shfl_xor_sync(0xFFFFFFFFu, bm0, 1));
        bm0 = fmaxf(bm0, __shfl_xor_sync(0xFFFFFFFFu, bm0, 2));
        bm1 = fmaxf(bm1, __shfl_xor_sync(0xFFFFFFFFu, bm1, 1));
        bm1 = fmaxf(bm1, __shfl_xor_sync(0xFFFFFFFFu, bm1, 2));

        const float nm0 = fmaxf(m0, bm0);
        const float nm1 = fmaxf(m1, bm1);
        const float sf0 = __expf(m0 - nm0);
        const float sf1 = __expf(m1 - nm1);

        float rs0 = 0.0f, rs1 = 0.0f;
#pragma unroll
        for (int nf = 0; nf < 16; nf++) {
            const float p0 = __expf(sacc[nf][0] - nm0);
            const float p1 = __expf(sacc[nf][1] - nm0);
            const float p2 = __expf(sacc[nf][2] - nm1);
            const float p3 = __expf(sacc[nf][3] - nm1);
            sacc[nf][0] = p0; sacc[nf][1] = p1;
            sacc[nf][2] = p2; sacc[nf][3] = p3;
            rs0 += p0 + p1; rs1 += p2 + p3;
        }
        rs0 += __shfl_xor_sync(0xFFFFFFFFu, rs0, 1);
        rs0 += __shfl_xor_sync(0xFFFFFFFFu, rs0, 2);
        rs1 += __shfl_xor_sync(0xFFFFFFFFu, rs1, 1);
        rs1 += __shfl_xor_sync(0xFFFFFFFFu, rs1, 2);

        l0 = l0 * sf0 + rs0;
        l1 = l1 * sf1 + rs1;
        m0 = nm0; m1 = nm1;
#pragma unroll
        for (int nf = 0; nf < 16; nf++) {
            oacc[nf][0] *= sf0; oacc[nf][1] *= sf0;
            oacc[nf][2] *= sf1; oacc[nf][3] *= sf1;
        }

#pragma unroll
        for (int kk = 0; kk < 8; kk++) {
            uint32_t a[4];
            a[0] = packh(sacc[2 * kk][0],     sacc[2 * kk][1]);
            a[1] = packh(sacc[2 * kk][2],     sacc[2 * kk][3]);
            a[2] = packh(sacc[2 * kk + 1][0], sacc[2 * kk + 1][1]);
            a[3] = packh(sacc[2 * kk + 1][2], sacc[2 * kk + 1][3]);
#pragma unroll
            for (int p = 0; p < 8; p++) {
                uint32_t b[4];
                const int r  = kk * 16 + ((l >> 3) & 1) * 8 + (l & 7);
                const int ck = 2 * p + (l >> 4);
                asm volatile(
                    "ldmatrix.sync.aligned.m8n8.x4.trans.shared.b16 {%0,%1,%2,%3}, [%4];"
                    : "=r"(b[0]), "=r"(b[1]), "=r"(b[2]), "=r"(b[3])
                    : "r"(sw256(sV, r, ck)));
                mma16816h(oacc[2 * p],     a, b[0], b[1]);
                mma16816h(oacc[2 * p + 1], a, b[2], b[3]);
            }
        }
        __syncthreads();
    }

    const float il0 = 1.0f / l0;
    const float il1 = 1.0f / l1;
    const float al  = __ldg(alpha + h);
    const size_t r0g = (size_t)(bq * 128 + w * 16 + (l >> 2));
    const size_t r1g = r0g + 8;

#pragma unroll
    for (int nf = 0; nf < 16; nf++) {
        const size_t cg = (size_t)(col0 + nf * 8 + (l & 3) * 2);
#pragma unroll
        for (int rr = 0; rr < 2; rr++) {
            const size_t row = rr ? r1g : r0g;
            const float il = rr ? il1 : il0;
            const float v0 = oacc[nf][rr * 2 + 0] * il + al * normed[row * D + cg];
            const float v1 = oacc[nf][rr * 2 + 1] * il + al * normed[row * D + cg + 1];
            *(uint32_t*)(outh + row * D + cg) = packh(v0, v1);
        }
    }
}

// ---------------------------------------------------------------------------
// Fused weight conversion: all 7 weights in one launch.
// ---------------------------------------------------------------------------
struct CvtParams {
    const float* src[7];
    __half*      dst[7];
    int          start[8];
};

__global__ __launch_bounds__(256) void convert_all_kernel(CvtParams p)
{
    const int b = blockIdx.x;
    int seg = 0;
#pragma unroll
    for (int s = 1; s < 7; s++)
        if (b >= p.start[s]) seg = s;
    const int i = (b - p.start[seg]) * 256 + threadIdx.x;
    const float4 v0 = ((const float4*)p.src[seg])[2 * i];
    const float4 v1 = ((const float4*)p.src[seg])[2 * i + 1];
    uint4 o;
    o.x = packh(v0.x, v0.y);
    o.y = packh(v0.z, v0.w);
    o.z = packh(v1.x, v1.y);
    o.w = packh(v1.z, v1.w);
    ((uint4*)p.dst[seg])[i] = o;
}

// rmsnorm -> f32 out + fp16 out, one block per row
__global__ __launch_bounds__(256) void rmsnorm_h_kernel(
    const float* __restrict__ x, const float* __restrict__ w,
    float* __restrict__ outf, __half* __restrict__ outh)
{
    __shared__ float red[256];
    const int r = blockIdx.x;
    const int tid = threadIdx.x;
    const float* xr = x + (size_t)r * D;

    float ss = 0.0f;
#pragma unroll
    for (int j4 = tid; j4 < D / 4; j4 += 256) {
        const float4 v = ((const float4*)xr)[j4];
        ss += v.x * v.x + v.y * v.y + v.z * v.z + v.w * v.w;
    }
    red[tid] = ss;
    __syncthreads();
    for (int s = 128; s > 0; s >>= 1) {
        if (tid < s) red[tid] += red[tid + s];
        __syncthreads();
    }
    const float sc = rsqrtf(red[0] / (float)D + 1e-6f);

#pragma unroll
    for (int j4 = tid; j4 < D / 4; j4 += 256) {
        const float4 v  = ((const float4*)xr)[j4];
        const float4 wv = ((const float4*)w)[j4];
        const float o0 = v.x * sc * wv.x;
        const float o1 = v.y * sc * wv.y;
        const float o2 = v.z * sc * wv.z;
        const float o3 = v.w * sc * wv.w;
        float4 of; of.x = o0; of.y = o1; of.z = o2; of.w = o3;
        ((float4*)(outf + (size_t)r * D))[j4] = of;
        uint2 oh;
        oh.x = packh(o0, o1);
        oh.y = packh(o2, o3);
        ((uint2*)(outh + (size_t)r * D))[j4] = oh;
    }
}

// h = silu(g)*u with fp16 g,u inputs -> fp16 out
__global__ __launch_bounds__(256) void silu_mul_h_kernel(
    const __half* __restrict__ g, const __half* __restrict__ u,
    __half* __restrict__ outh)
{
    const size_t i = (size_t)blockIdx.x * 256 + threadIdx.x;
    const uint2 gv = ((const uint2*)g)[i];
    const uint2 uv = ((const uint2*)u)[i];
    const __half2 g0 = *(const __half2*)&gv.x;
    const __half2 g1 = *(const __half2*)&gv.y;
    const __half2 u0 = *(const __half2*)&uv.x;
    const __half2 u1 = *(const __half2*)&uv.y;
    const float gx = __half2float(g0.x), gy = __half2float(g0.y);
    const float gz = __half2float(g1.x), gw = __half2float(g1.y);
    const float a0 = gx / (1.0f + __expf(-gx)) * __half2float(u0.x);
    const float a1 = gy / (1.0f + __expf(-gy)) * __half2float(u0.y);
    const float a2 = gz / (1.0f + __expf(-gz)) * __half2float(u1.x);
    const float a3 = gw / (1.0f + __expf(-gw)) * __half2float(u1.y);
    uint2 o;
    o.x = packh(a0, a1);
    o.y = packh(a2, a3);
    ((uint2*)outh)[i] = o;
}

// ---------------------------------------------------------------------------
// Launch
// ---------------------------------------------------------------------------
extern "C" void kernel_launch(void* const* d_in, const int* in_sizes, int n_in,
                              void* d_out, int out_size)
{
    (void)in_sizes; (void)n_in; (void)out_size;

    const float* x     = (const float*)d_in[0];
    const float* wn_a  = (const float*)d_in[1];
    const float* wn_m  = (const float*)d_in[2];
    const float* Wq    = (const float*)d_in[3];
    const float* sq    = (const float*)d_in[4];
    const float* Wk    = (const float*)d_in[5];
    const float* sk    = (const float*)d_in[6];
    const float* Wv    = (const float*)d_in[7];
    const float* sv    = (const float*)d_in[8];
    const float* Wo    = (const float*)d_in[9];
    const float* so    = (const float*)d_in[10];
    const float* Wg    = (const float*)d_in[11];
    const float* sg    = (const float*)d_in[12];
    const float* Wu    = (const float*)d_in[13];
    const float* su    = (const float*)d_in[14];
    const float* Wd    = (const float*)d_in[15];
    const float* sd    = (const float*)d_in[16];
    const float* alpha = (const float*)d_in[17];
    float* out = (float*)d_out;

    float *normed, *x1;
    cudaGetSymbolAddress((void**)&normed, g_normed);
    cudaGetSymbolAddress((void**)&x1,     g_x1);

    __half *qh, *kh, *vh, *gateh, *uph, *wq, *wk, *wv, *wo, *wg, *wu, *wd, *act;
    cudaGetSymbolAddress((void**)&qh, g_qh);
    cudaGetSymbolAddress((void**)&kh, g_kh);
    cudaGetSymbolAddress((void**)&vh, g_vh);
    cudaGetSymbolAddress((void**)&gateh, g_gate_h);
    cudaGetSymbolAddress((void**)&uph,   g_up_h);
    cudaGetSymbolAddress((void**)&wq, g_wq_h);
    cudaGetSymbolAddress((void**)&wk, g_wk_h);
    cudaGetSymbolAddress((void**)&wv, g_wv_h);
    cudaGetSymbolAddress((void**)&wo, g_wo_h);
    cudaGetSymbolAddress((void**)&wg, g_wg_h);
    cudaGetSymbolAddress((void**)&wu, g_wu_h);
    cudaGetSymbolAddress((void**)&wd, g_wd_h);
    cudaGetSymbolAddress((void**)&act, g_act);

    cudaFuncSetAttribute(mma_gemm, cudaFuncAttributeMaxDynamicSharedMemorySize,
                         MMA_SMEM);
    cudaFuncSetAttribute(flash_attn, cudaFuncAttributeMaxDynamicSharedMemorySize,
                         FL_SMEM);

    const float inv_sqrt_dh = 0.08838834764831845f;  // 1/sqrt(128)

    // 0. all weights -> fp16 in one launch (exact for ternary)
    const int bDD = D * D / 8 / 256;
    const int bFD = DFF * D / 8 / 256;
    CvtParams cp;
    cp.src[0] = Wq; cp.dst[0] = wq;
    cp.src[1] = Wk; cp.dst[1] = wk;
    cp.src[2] = Wv; cp.dst[2] = wv;
    cp.src[3] = Wo; cp.dst[3] = wo;
    cp.src[4] = Wg; cp.dst[4] = wg;
    cp.src[5] = Wu; cp.dst[5] = wu;
    cp.src[6] = Wd; cp.dst[6] = wd;
    cp.start[0] = 0;
    cp.start[1] = bDD;
    cp.start[2] = 2 * bDD;
    cp.start[3] = 3 * bDD;
    cp.start[4] = 4 * bDD;
    cp.start[5] = 4 * bDD + bFD;
    cp.start[6] = 4 * bDD + 2 * bFD;
    cp.start[7] = 4 * bDD + 3 * bFD;
    convert_all_kernel<<<cp.start[7], 256>>>(cp);

    // 1. rmsnorm (f32 + fp16 fused)
    rmsnorm_h_kernel<<<S, 256>>>(x, wn_a, normed, act);

    // 2. QKV fused: 3 segments, grid (48, 16), 128 threads
    {
        GemmSegs p = {};
        p.B[0] = wq; p.B[1] = wk; p.B[2] = wv;
        p.Ch[0] = qh; p.Ch[1] = kh; p.Ch[2] = vh;
        p.scale[0] = sq; p.scale[1] = sk; p.scale[2] = sv;
        p.sconst[0] = inv_sqrt_dh; p.sconst[1] = 1.0f; p.sconst[2] = 1.0f;
        mma_gemm<<<dim3(3 * D / 128, S / 128), 128, MMA_SMEM>>>(
            act, p, D / 128, D, D);
    }

    // 3. flash attention -> fp16 (attn_out + alpha*normed)
    flash_attn<<<dim3(S / 128, H), 256, FL_SMEM>>>(
        qh, kh, vh, normed, alpha, act);

    // 4. x1 = x + attn @ Wo^T * so
    {
        GemmSegs p = {};
        p.B[0] = wo;
        p.Cf = x1; p.R = x;
        p.scale[0] = so; p.sconst[0] = 1.0f;
        mma_gemm<<<dim3(D / 128, S / 128), 128, MMA_SMEM>>>(
            act, p, D / 128, D, D);
    }

    // 5. mlp norm (fused fp16)
    rmsnorm_h_kernel<<<S, 256>>>(x1, wn_m, normed, act);

    // 6. gate + up fused: 2 segments, grid (128, 16)
    {
        GemmSegs p = {};
        p.B[0] = wg; p.B[1] = wu;
        p.Ch[0] = gateh; p.Ch[1] = uph;
        p.scale[0] = sg; p.scale[1] = su;
        p.sconst[0] = 1.0f; p.sconst[1] = 1.0f;
        mma_gemm<<<dim3(2 * DFF / 128, S / 128), 128, MMA_SMEM>>>(
            act, p, DFF / 128, D, DFF);
    }

    // 7. silu*up (fp16 in) -> fp16
    silu_mul_h_kernel<<<(S * DFF / 4) / 256, 256>>>(gateh, uph, act);

    // 8. out = x1 + h @ Wd^T * sd
    {
        GemmSegs p = {};
        p.B[0] = wd;
        p.Cf = out; p.R = x1;
        p.scale[0] = sd; p.sconst[0] = 1.0f;
        mma_gemm<<<dim3(D / 128, S / 128), 128, MMA_SMEM>>>(
            act, p, DFF / 128, DFF, D);
    }
}